// round 10
// baseline (speedup 1.0000x reference)
#include <cuda_runtime.h>
#include <cuda_fp16.h>

#define NUM_DRUG 50000
#define NUM_CELL 20000
#define HDIM     128
#define NEDGE    600000
#define NBATCH   4096

#define G8_DRUG (NUM_DRUG / 8)   // 6250 warp-tiles
#define G8_CELL (NUM_CELL / 8)   // 2500

#define GEMM_BLOCKS 296
#define ND_BLOCKS   212          // drug share of gemm blocks (50k/70k rows)
#define WARPS       8            // 256 threads / block
#define GEMM_SMEM ((HDIM * HDIM + WARPS * 8 * HDIM) * sizeof(float))  // 96 KB

// ---------------- scratch (device globals; no runtime allocation) ----------
__device__ __align__(16) float g_hA_drug[NUM_DRUG * HDIM];
__device__ __align__(16) float g_hA_cell[NUM_CELL * HDIM];
__device__ __align__(16) float g_hB_drug[NUM_DRUG * HDIM];
__device__ __align__(16) float g_hB_cell[NUM_CELL * HDIM];
__device__ __align__(16) float g_acc[(NUM_DRUG + NUM_CELL) * HDIM];  // mean msgs
__device__ __align__(16) __half g_he_drug[NUM_DRUG * HDIM];   // fp16 gather tables
__device__ __align__(16) __half g_he_cell[NUM_CELL * HDIM];
__device__ __align__(16) __half g_h1_drug[NUM_DRUG * HDIM];
__device__ __align__(16) __half g_h1_cell[NUM_CELL * HDIM];
__device__ __align__(16) float g_WT_td[HDIM * HDIM];
__device__ __align__(16) float g_WT_dt[HDIM * HDIM];
__device__ int g_off_drug[NUM_DRUG + 1];
__device__ int g_off_cell[NUM_CELL + 1];
__device__ int g_cur_drug[NUM_DRUG];
__device__ int g_cur_cell[NUM_CELL];
__device__ int g_csr_td[NEDGE];
__device__ int g_csr_dt[NEDGE];

// ---------------- f32x2 helpers --------------------------------------------
__device__ __forceinline__ unsigned long long splat2(float x) {
    unsigned long long r; unsigned xi = __float_as_uint(x);
    asm("mov.b64 %0, {%1, %1};" : "=l"(r) : "r"(xi));
    return r;
}
__device__ __forceinline__ unsigned long long fma2(unsigned long long a,
                                                   unsigned long long b,
                                                   unsigned long long c) {
    unsigned long long d;
    asm("fma.rn.f32x2 %0, %1, %2, %3;" : "=l"(d) : "l"(a), "l"(b), "l"(c));
    return d;
}
__device__ __forceinline__ unsigned long long addf2(unsigned long long a,
                                                    unsigned long long b) {
    unsigned long long d;
    asm("add.rn.f32x2 %0, %1, %2;" : "=l"(d) : "l"(a), "l"(b));
    return d;
}
__device__ __forceinline__ float lo2(unsigned long long v) {
    return __uint_as_float((unsigned)(v & 0xffffffffull));
}
__device__ __forceinline__ float hi2(unsigned long long v) {
    return __uint_as_float((unsigned)(v >> 32));
}
// half2 bits -> packed f32x2 (as ull)
__device__ __forceinline__ unsigned long long h2f2(unsigned h) {
    float2 f = __half22float2(*reinterpret_cast<const __half2*>(&h));
    unsigned long long r;
    asm("mov.b64 %0, {%1, %2};" : "=l"(r) : "f"(f.x), "f"(f.y));
    return r;
}

// ---------------- CSR hist + emb->fp16 convert (one launch) ----------------
#define EB2   ((2 * NEDGE + 255) / 256)                       // 4688 blocks
#define CONVB (((NUM_DRUG + NUM_CELL) * HDIM / 4) / 256)      // 8750 blocks
__global__ void hist_conv_kernel(const int* __restrict__ dstA, int* __restrict__ cntA,
                                 const int* __restrict__ dstB, int* __restrict__ cntB,
                                 const float* __restrict__ ed, __half* __restrict__ hd16,
                                 const float* __restrict__ ec, __half* __restrict__ hc16)
{
    long long i = (long long)blockIdx.x * blockDim.x + threadIdx.x;
    if (i < NEDGE) { atomicAdd(&cntA[dstA[i]], 1); return; }
    if (i < 2 * NEDGE) { atomicAdd(&cntB[dstB[i - NEDGE]], 1); return; }
    long long j = i - 2 * NEDGE;   // float4 index
    const long long nd4 = (long long)NUM_DRUG * HDIM / 4;
    const long long nc4 = (long long)NUM_CELL * HDIM / 4;
    if (j < nd4) {
        float4 v = reinterpret_cast<const float4*>(ed)[j];
        uint2 o;
        *reinterpret_cast<__half2*>(&o.x) = __floats2half2_rn(v.x, v.y);
        *reinterpret_cast<__half2*>(&o.y) = __floats2half2_rn(v.z, v.w);
        reinterpret_cast<uint2*>(hd16)[j] = o;
    } else if (j < nd4 + nc4) {
        long long k = j - nd4;
        float4 v = reinterpret_cast<const float4*>(ec)[k];
        uint2 o;
        *reinterpret_cast<__half2*>(&o.x) = __floats2half2_rn(v.x, v.y);
        *reinterpret_cast<__half2*>(&o.y) = __floats2half2_rn(v.z, v.w);
        reinterpret_cast<uint2*>(hc16)[k] = o;
    }
}

// blocks 0,1: coarsened scans. blocks 2,3: weight transposes.
__global__ void scan_transpose_kernel(const int* __restrict__ cntA, int* __restrict__ offA,
                                      const int* __restrict__ cntB, int* __restrict__ offB,
                                      const float* __restrict__ Wa, float* __restrict__ WTa,
                                      const float* __restrict__ Wb, float* __restrict__ WTb)
{
    int t = threadIdx.x;
    if (blockIdx.x >= 2) {
        const float* W = blockIdx.x == 2 ? Wa : Wb;
        float* WT      = blockIdx.x == 2 ? WTa : WTb;
        #pragma unroll
        for (int i = t; i < HDIM * HDIM; i += 1024) {
            int k = i & 127, out = i >> 7;
            WT[k * HDIM + out] = W[out * HDIM + k];
        }
        return;
    }
    const int* cnt = blockIdx.x == 0 ? cntA : cntB;
    int* off       = blockIdx.x == 0 ? offA : offB;
    const int n    = blockIdx.x == 0 ? NUM_DRUG : NUM_CELL;

    __shared__ int ws[32];
    __shared__ int s_carry;
    int lane = t & 31, w = t >> 5;
    if (t == 0) s_carry = 0;
    __syncthreads();

    for (int base = 0; base < n; base += 1024 * 8) {
        int idx = base + t * 8;
        int v[8];
        #pragma unroll
        for (int j = 0; j < 8; j++)
            v[j] = (idx + j < n) ? cnt[idx + j] : 0;
        #pragma unroll
        for (int j = 1; j < 8; j++) v[j] += v[j - 1];
        int tot = v[7];
        int x = tot;
        #pragma unroll
        for (int o = 1; o < 32; o <<= 1) {
            int y = __shfl_up_sync(0xffffffffu, x, o);
            if (lane >= o) x += y;
        }
        if (lane == 31) ws[w] = x;
        __syncthreads();
        if (w == 0) {
            int s = ws[lane];
            #pragma unroll
            for (int o = 1; o < 32; o <<= 1) {
                int y = __shfl_up_sync(0xffffffffu, s, o);
                if (lane >= o) s += y;
            }
            ws[lane] = s;
        }
        __syncthreads();
        int prefix = (x - tot) + (w ? ws[w - 1] : 0) + s_carry;
        #pragma unroll
        for (int j = 0; j < 8; j++)
            if (idx + j < n) off[idx + j + 1] = prefix + v[j];
        __syncthreads();
        if (t == 0) s_carry += ws[31];
        __syncthreads();
    }
    if (t == 0) off[0] = 0;
}

__global__ void fill2_kernel(const int* __restrict__ srcA, const int* __restrict__ dstA,
                             const int* __restrict__ offA, int* __restrict__ curA,
                             int* __restrict__ csrA,
                             const int* __restrict__ srcB, const int* __restrict__ dstB,
                             const int* __restrict__ offB, int* __restrict__ curB,
                             int* __restrict__ csrB)
{
    int tid = blockIdx.x * blockDim.x + threadIdx.x;
    int i0 = tid * 2;
    if (i0 < NEDGE) {
        int i1 = i0 + 1;
        int d0 = dstA[i0];
        int d1 = (i1 < NEDGE) ? dstA[i1] : -1;
        int s0 = srcA[i0];
        int s1 = (i1 < NEDGE) ? srcA[i1] : 0;
        int p0 = offA[d0] + atomicAdd(&curA[d0], 1);
        int p1 = (d1 >= 0) ? (offA[d1] + atomicAdd(&curA[d1], 1)) : 0;
        csrA[p0] = s0;
        if (d1 >= 0) csrA[p1] = s1;
    } else if (i0 < 2 * NEDGE) {
        int j0 = i0 - NEDGE, j1 = j0 + 1;
        int d0 = dstB[j0];
        int d1 = (j1 < NEDGE) ? dstB[j1] : -1;
        int s0 = srcB[j0];
        int s1 = (j1 < NEDGE) ? srcB[j1] : 0;
        int p0 = offB[d0] + atomicAdd(&curB[d0], 1);
        int p1 = (d1 >= 0) ? (offB[d1] + atomicAdd(&curB[d1], 1)) : 0;
        csrB[p0] = s0;
        if (d1 >= 0) csrB[p1] = s1;
    }
}

// ---------------- gather-mean (fp16 source, fp32 accumulate) ---------------
// One warp per dst row, both sides in one launch. L2-byte-bound -> fp16 halves it.
__global__ void __launch_bounds__(256)
gather_kernel(const __half* __restrict__ hd16, const __half* __restrict__ hc16,
              float* __restrict__ acc,
              const int* __restrict__ off_d, const int* __restrict__ csr_d,
              const int* __restrict__ off_c, const int* __restrict__ csr_c)
{
    const int gw   = (blockIdx.x * blockDim.x + threadIdx.x) >> 5;  // row id
    const int lane = threadIdx.x & 31;
    const bool isD = gw < NUM_DRUG;
    const __half* src = isD ? hc16 : hd16;   // gather from the other side
    const int* off    = isD ? off_d : off_c;
    const int* csr    = isD ? csr_d : csr_c;
    const int r       = isD ? gw : gw - NUM_DRUG;

    const uint2* src2 = reinterpret_cast<const uint2*>(src);  // 8B per lane
    int jb = off[r], je = off[r + 1];
    unsigned long long xy0 = 0, xy1 = 0, xy2 = 0, xy3 = 0;
    unsigned long long zw0 = 0, zw1 = 0, zw2 = 0, zw3 = 0;
    int j = jb;
    for (; j + 8 <= je; j += 8) {
        int s0 = csr[j],   s1 = csr[j+1], s2 = csr[j+2], s3 = csr[j+3];
        int s4 = csr[j+4], s5 = csr[j+5], s6 = csr[j+6], s7 = csr[j+7];
        uint2 v0 = src2[s0 * 32 + lane];
        uint2 v1 = src2[s1 * 32 + lane];
        uint2 v2 = src2[s2 * 32 + lane];
        uint2 v3 = src2[s3 * 32 + lane];
        uint2 v4 = src2[s4 * 32 + lane];
        uint2 v5 = src2[s5 * 32 + lane];
        uint2 v6 = src2[s6 * 32 + lane];
        uint2 v7 = src2[s7 * 32 + lane];
        xy0 = addf2(xy0, h2f2(v0.x)); zw0 = addf2(zw0, h2f2(v0.y));
        xy1 = addf2(xy1, h2f2(v1.x)); zw1 = addf2(zw1, h2f2(v1.y));
        xy2 = addf2(xy2, h2f2(v2.x)); zw2 = addf2(zw2, h2f2(v2.y));
        xy3 = addf2(xy3, h2f2(v3.x)); zw3 = addf2(zw3, h2f2(v3.y));
        xy0 = addf2(xy0, h2f2(v4.x)); zw0 = addf2(zw0, h2f2(v4.y));
        xy1 = addf2(xy1, h2f2(v5.x)); zw1 = addf2(zw1, h2f2(v5.y));
        xy2 = addf2(xy2, h2f2(v6.x)); zw2 = addf2(zw2, h2f2(v6.y));
        xy3 = addf2(xy3, h2f2(v7.x)); zw3 = addf2(zw3, h2f2(v7.y));
    }
    if (j + 4 <= je) {
        int s0 = csr[j], s1 = csr[j+1], s2 = csr[j+2], s3 = csr[j+3];
        uint2 v0 = src2[s0 * 32 + lane];
        uint2 v1 = src2[s1 * 32 + lane];
        uint2 v2 = src2[s2 * 32 + lane];
        uint2 v3 = src2[s3 * 32 + lane];
        xy0 = addf2(xy0, h2f2(v0.x)); zw0 = addf2(zw0, h2f2(v0.y));
        xy1 = addf2(xy1, h2f2(v1.x)); zw1 = addf2(zw1, h2f2(v1.y));
        xy2 = addf2(xy2, h2f2(v2.x)); zw2 = addf2(zw2, h2f2(v2.y));
        xy3 = addf2(xy3, h2f2(v3.x)); zw3 = addf2(zw3, h2f2(v3.y));
        j += 4;
    }
    for (; j < je; j++) {
        uint2 v = src2[csr[j] * 32 + lane];
        xy0 = addf2(xy0, h2f2(v.x)); zw0 = addf2(zw0, h2f2(v.y));
    }

    unsigned long long XY = addf2(addf2(xy0, xy1), addf2(xy2, xy3));
    unsigned long long ZW = addf2(addf2(zw0, zw1), addf2(zw2, zw3));
    int deg = je - jb;
    float inv = 1.0f / (float)(deg < 1 ? 1 : deg);
    float4 a;
    a.x = lo2(XY) * inv; a.y = hi2(XY) * inv;
    a.z = lo2(ZW) * inv; a.w = hi2(ZW) * inv;
    reinterpret_cast<float4*>(acc)[gw * 32 + lane] = a;
}

// ---------------- GEMM + residual + LN + ReLU (+ fp16 mirror out) ----------
__global__ void __launch_bounds__(256, 2)
gemm_ln_kernel(const float* __restrict__ acc,           // [70000][128] means
               const float* __restrict__ hd_in, const float* __restrict__ hc_in,
               float* __restrict__ hd_out, float* __restrict__ hc_out,
               __half* __restrict__ hd16_out, __half* __restrict__ hc16_out,
               const float* __restrict__ WT_td, const float* __restrict__ WT_dt,
               const float* __restrict__ gd, const float* __restrict__ bd,
               const float* __restrict__ gc, const float* __restrict__ bc)
{
    const bool isD = blockIdx.x < ND_BLOCKS;
    const float* accp = isD ? acc : acc + (size_t)NUM_DRUG * HDIM;
    const float* hold = isD ? hd_in : hc_in;
    float* outp       = isD ? hd_out : hc_out;
    __half* outp16    = isD ? hd16_out : hc16_out;
    const float* WTg  = isD ? WT_td : WT_dt;
    const float* gam  = isD ? gd : gc;
    const float* bet  = isD ? bd : bc;
    const int ng8     = isD ? G8_DRUG : G8_CELL;
    const int nb      = isD ? ND_BLOCKS : (GEMM_BLOCKS - ND_BLOCKS);
    const int bid     = isD ? blockIdx.x : blockIdx.x - ND_BLOCKS;

    extern __shared__ float sm[];
    float* WT = sm;                                  // [128][128]
    const int t = threadIdx.x, lane = t & 31, w = t >> 5;
    float* XS = sm + HDIM * HDIM + w * (8 * HDIM);   // warp-private [8][128]
    const int c0 = 4 * lane;

    {
        const float4* s4 = reinterpret_cast<const float4*>(WTg);
        float4* d4 = reinterpret_cast<float4*>(WT);
        #pragma unroll
        for (int i = t; i < HDIM * HDIM / 4; i += 256) d4[i] = s4[i];
    }
    const float4 g4 = reinterpret_cast<const float4*>(gam)[lane];
    const float4 b4 = reinterpret_cast<const float4*>(bet)[lane];
    __syncthreads();

    const float4* acc4  = reinterpret_cast<const float4*>(accp);
    const float4* hold4 = reinterpret_cast<const float4*>(hold);
    float4* out4        = reinterpret_cast<float4*>(outp);
    uint2* out16        = reinterpret_cast<uint2*>(outp16);

    for (int wg = bid * WARPS + w; wg < ng8; wg += nb * WARPS) {
        const int row0 = wg * 8;

        // ---- load 8 mean rows into XS (coalesced) ----
        #pragma unroll
        for (int i = 0; i < 8; i++)
            *reinterpret_cast<float4*>(&XS[i * HDIM + c0]) = acc4[(row0 + i) * 32 + lane];
        __syncwarp();

        // ---- GEMM: y[i][out] = sum_k x[i][k] * W[out][k], f32x2 packed ----
        unsigned long long acc2[8][2];
        #pragma unroll
        for (int i = 0; i < 8; i++) { acc2[i][0] = 0ull; acc2[i][1] = 0ull; }

        for (int kt = 0; kt < HDIM; kt += 4) {
            float4 xv[8];
            #pragma unroll
            for (int i = 0; i < 8; i++)
                xv[i] = *reinterpret_cast<const float4*>(&XS[i * HDIM + kt]);
            #pragma unroll
            for (int kk = 0; kk < 4; kk++) {
                ulonglong2 wv = *reinterpret_cast<const ulonglong2*>(
                    &WT[(kt + kk) * HDIM + c0]);
                #pragma unroll
                for (int i = 0; i < 8; i++) {
                    float xs = (kk == 0) ? xv[i].x : (kk == 1) ? xv[i].y
                             : (kk == 2) ? xv[i].z : xv[i].w;
                    unsigned long long s2 = splat2(xs);
                    acc2[i][0] = fma2(s2, wv.x, acc2[i][0]);
                    acc2[i][1] = fma2(s2, wv.y, acc2[i][1]);
                }
            }
        }

        // ---- epilogue: residual + LayerNorm + ReLU (+ fp16 mirror) ----
        #pragma unroll
        for (int i = 0; i < 8; i++) {
            int grow = row0 + i;
            float4 hv = hold4[grow * 32 + lane];
            float y0 = lo2(acc2[i][0]) + hv.x;
            float y1 = hi2(acc2[i][0]) + hv.y;
            float y2 = lo2(acc2[i][1]) + hv.z;
            float y3 = hi2(acc2[i][1]) + hv.w;

            float s = y0 + y1 + y2 + y3;
            float q = y0*y0 + y1*y1 + y2*y2 + y3*y3;
            #pragma unroll
            for (int o = 16; o; o >>= 1) {
                s += __shfl_xor_sync(0xffffffffu, s, o);
                q += __shfl_xor_sync(0xffffffffu, q, o);
            }
            float mu  = s * (1.0f / HDIM);
            float var = q * (1.0f / HDIM) - mu * mu;
            float rs  = rsqrtf(var + 1e-5f);
            float4 o4;
            o4.x = (y0 - mu) * rs * g4.x + b4.x; o4.x = o4.x > 0.f ? o4.x : 0.f;
            o4.y = (y1 - mu) * rs * g4.y + b4.y; o4.y = o4.y > 0.f ? o4.y : 0.f;
            o4.z = (y2 - mu) * rs * g4.z + b4.z; o4.z = o4.z > 0.f ? o4.z : 0.f;
            o4.w = (y3 - mu) * rs * g4.w + b4.w; o4.w = o4.w > 0.f ? o4.w : 0.f;
            out4[grow * 32 + lane] = o4;
            uint2 p;
            *reinterpret_cast<__half2*>(&p.x) = __floats2half2_rn(o4.x, o4.y);
            *reinterpret_cast<__half2*>(&p.y) = __floats2half2_rn(o4.z, o4.w);
            out16[grow * 32 + lane] = p;
        }
        __syncwarp();   // XS reused next iteration
    }
}

// ---------------- final head -------------------------------------------------
__global__ void final_kernel(const float* __restrict__ hd,
                             const float* __restrict__ hc,
                             const int* __restrict__ did,
                             const int* __restrict__ cid,
                             const float* __restrict__ wf,
                             const float* __restrict__ bf,
                             float* __restrict__ out, int nb)
{
    int warp = (blockIdx.x * blockDim.x + threadIdx.x) >> 5;
    int lane = threadIdx.x & 31;
    if (warp >= nb) return;
    int d = did[warp], c = cid[warp];
    float4 a  = reinterpret_cast<const float4*>(hd)[d * 32 + lane];
    float4 w1 = reinterpret_cast<const float4*>(wf)[lane];
    float4 b4 = reinterpret_cast<const float4*>(hc)[c * 32 + lane];
    float4 w2 = reinterpret_cast<const float4*>(wf)[32 + lane];
    float s = a.x * w1.x + a.y * w1.y + a.z * w1.z + a.w * w1.w
            + b4.x * w2.x + b4.y * w2.y + b4.z * w2.z + b4.w * w2.w;
    #pragma unroll
    for (int o = 16; o; o >>= 1) s += __shfl_xor_sync(0xffffffffu, s, o);
    if (lane == 0) {
        float x = s + bf[0];
        out[warp] = 1.0f / (1.0f + expf(-x));
    }
}

// ---------------------------------------------------------------------------
extern "C" void kernel_launch(void* const* d_in, const int* in_sizes, int n_in,
                              void* d_out, int out_size)
{
    const float* emb_drug  = (const float*)d_in[0];
    const float* emb_cell  = (const float*)d_in[1];
    const float* W_dt      = (const float*)d_in[2];
    const float* W_td      = (const float*)d_in[3];
    const float* ln_drug_g = (const float*)d_in[4];
    const float* ln_drug_b = (const float*)d_in[5];
    const float* ln_cell_g = (const float*)d_in[6];
    const float* ln_cell_b = (const float*)d_in[7];
    const float* W_final_w = (const float*)d_in[8];
    const float* W_final_b = (const float*)d_in[9];
    const int* edge_dt_src = (const int*)d_in[10];
    const int* edge_dt_dst = (const int*)d_in[11];
    const int* edge_td_src = (const int*)d_in[12];
    const int* edge_td_dst = (const int*)d_in[13];
    const int* drug_ids    = (const int*)d_in[14];
    const int* cell_ids    = (const int*)d_in[15];
    float* out = (float*)d_out;

    float *hA_d, *hA_c, *hB_d, *hB_c, *accb, *WT_td, *WT_dt;
    __half *he_d, *he_c, *h1_d, *h1_c;
    int *off_d, *off_c, *cur_d, *cur_c, *csr_td, *csr_dt;
    cudaGetSymbolAddress((void**)&hA_d,   g_hA_drug);
    cudaGetSymbolAddress((void**)&hA_c,   g_hA_cell);
    cudaGetSymbolAddress((void**)&hB_d,   g_hB_drug);
    cudaGetSymbolAddress((void**)&hB_c,   g_hB_cell);
    cudaGetSymbolAddress((void**)&accb,   g_acc);
    cudaGetSymbolAddress((void**)&he_d,   g_he_drug);
    cudaGetSymbolAddress((void**)&he_c,   g_he_cell);
    cudaGetSymbolAddress((void**)&h1_d,   g_h1_drug);
    cudaGetSymbolAddress((void**)&h1_c,   g_h1_cell);
    cudaGetSymbolAddress((void**)&WT_td,  g_WT_td);
    cudaGetSymbolAddress((void**)&WT_dt,  g_WT_dt);
    cudaGetSymbolAddress((void**)&off_d,  g_off_drug);
    cudaGetSymbolAddress((void**)&off_c,  g_off_cell);
    cudaGetSymbolAddress((void**)&cur_d,  g_cur_drug);
    cudaGetSymbolAddress((void**)&cur_c,  g_cur_cell);
    cudaGetSymbolAddress((void**)&csr_td, g_csr_td);
    cudaGetSymbolAddress((void**)&csr_dt, g_csr_dt);

    cudaFuncSetAttribute(gemm_ln_kernel,
                         cudaFuncAttributeMaxDynamicSharedMemorySize,
                         (int)GEMM_SMEM);

    const int gather_blocks = (NUM_DRUG + NUM_CELL) / 8;   // 8750

    // ---------------- CSR build + fp16 convert ----------------
    cudaMemsetAsync(cur_d, 0, NUM_DRUG * sizeof(int));
    cudaMemsetAsync(cur_c, 0, NUM_CELL * sizeof(int));
    hist_conv_kernel<<<EB2 + CONVB, 256>>>(edge_td_dst, cur_d, edge_dt_dst, cur_c,
                                           emb_drug, he_d, emb_cell, he_c);
    scan_transpose_kernel<<<4, 1024>>>(cur_d, off_d, cur_c, off_c,
                                       W_td, WT_td, W_dt, WT_dt);
    cudaMemsetAsync(cur_d, 0, NUM_DRUG * sizeof(int));
    cudaMemsetAsync(cur_c, 0, NUM_CELL * sizeof(int));
    fill2_kernel<<<(NEDGE + 255) / 256, 256>>>(
        edge_td_src, edge_td_dst, off_d, cur_d, csr_td,
        edge_dt_src, edge_dt_dst, off_c, cur_c, csr_dt);

    // ---------------- layer 0 ----------------
    gather_kernel<<<gather_blocks, 256>>>(he_d, he_c, accb,
                                          off_d, csr_td, off_c, csr_dt);
    gemm_ln_kernel<<<GEMM_BLOCKS, 256, GEMM_SMEM>>>(
        accb, emb_drug, emb_cell, hA_d, hA_c, h1_d, h1_c, WT_td, WT_dt,
        ln_drug_g, ln_drug_b, ln_cell_g, ln_cell_b);

    // ---------------- layer 1 ----------------
    gather_kernel<<<gather_blocks, 256>>>(h1_d, h1_c, accb,
                                          off_d, csr_td, off_c, csr_dt);
    gemm_ln_kernel<<<GEMM_BLOCKS, 256, GEMM_SMEM>>>(
        accb, hA_d, hA_c, hB_d, hB_c, he_d, he_c, WT_td, WT_dt,
        ln_drug_g, ln_drug_b, ln_cell_g, ln_cell_b);

    // ---------------- final head ----------------
    final_kernel<<<(NBATCH * 32) / 256, 256>>>(hB_d, hB_c, drug_ids, cell_ids,
                                               W_final_w, W_final_b, out, NBATCH);
}